// round 9
// baseline (speedup 1.0000x reference)
#include <cuda_runtime.h>
#include <cuda_bf16.h>
#include <cstdint>

// Closed-form per-(batch,class) reduction of the symmetric-pair loss.
// For a group of n points of one symmetric class (c in {0,1,2}), with
// u_i = x_i - CENTER_X:
//   sum_{i<j} (u_i+u_j)^2 = (n-2)*Sum(u^2) + (Sum u)^2
//   sum_{i<j} (y_i-y_j)^2 =  n   *Sum(y^2) - (Sum y)^2
//   #pairs                =  n(n-1)/2
// Both identities are exactly 0 for n in {0,1}.
//
// kernel1: one CTA per batch, all-float math, warp-parallel cross-warp
//          reduce (no serial FP64 chain).  [exact R5 configuration]
// finalize: PDL-overlapped, single warp, no smem/syncthreads; double only
//          for the final 256-element accumulation.

#define CENTER_X 0.5f
#define BATCH 256
#define NPTS  512

__device__ float2 g_partial[BATCH];  // (loss, count) per batch

__global__ void __launch_bounds__(256) sym_per_batch(const float* __restrict__ kp,
                                                     const int* __restrict__ cls) {
    const int b = blockIdx.x;
    const int t = threadIdx.x;

    // Each thread handles 2 consecutive points: 1x float4 + 1x int2.
    const float4 p = reinterpret_cast<const float4*>(kp)[(size_t)b * 256 + t];
    const int2   c = reinterpret_cast<const int2*>(cls)[(size_t)b * 256 + t];

    float acc[15];  // [class][su, su2, sy, sy2, cn]
#pragma unroll
    for (int k = 0; k < 15; k++) acc[k] = 0.0f;

    const float ux[2] = {p.x - CENTER_X, p.z - CENTER_X};
    const float yy[2] = {p.y, p.w};
    const int   cc[2] = {c.x, c.y};
#pragma unroll
    for (int j = 0; j < 2; j++) {
#pragma unroll
        for (int k = 0; k < 3; k++) {
            if (cc[j] == k) {
                acc[k * 5 + 0] += ux[j];
                acc[k * 5 + 1]  = fmaf(ux[j], ux[j], acc[k * 5 + 1]);
                acc[k * 5 + 2] += yy[j];
                acc[k * 5 + 3]  = fmaf(yy[j], yy[j], acc[k * 5 + 3]);
                acc[k * 5 + 4] += 1.0f;
            }
        }
    }

    // Intra-warp reduction (shuffles).
#pragma unroll
    for (int off = 16; off > 0; off >>= 1) {
#pragma unroll
        for (int k = 0; k < 15; k++)
            acc[k] += __shfl_down_sync(0xffffffffu, acc[k], off);
    }

    // Cross-warp via shared memory (8 warps).
    __shared__ float sf[8][16];  // padded row to dodge conflicts
    __shared__ float stot[16];
    const int wid = t >> 5, lid = t & 31;
    if (lid == 0) {
#pragma unroll
        for (int k = 0; k < 15; k++) sf[wid][k] = acc[k];
    }
    __syncthreads();

    // Warp 0, lanes 0..14: each lane sums one accumulator type across 8 warps.
    if (wid == 0) {
        if (lid < 15) {
            float s = 0.0f;
#pragma unroll
            for (int w = 0; w < 8; w++) s += sf[w][lid];
            stot[lid] = s;
        }
        __syncwarp();
        if (lid == 0) {
            float loss = 0.0f, count = 0.0f;
#pragma unroll
            for (int k = 0; k < 3; k++) {
                const float SU  = stot[k * 5 + 0];
                const float SU2 = stot[k * 5 + 1];
                const float SY  = stot[k * 5 + 2];
                const float SY2 = stot[k * 5 + 3];
                const float n   = stot[k * 5 + 4];
                loss  += (n - 2.0f) * SU2 + SU * SU + n * SY2 - SY * SY;
                count += n * (n - 1.0f) * 0.5f;
            }
            g_partial[b] = make_float2(loss, count);
        }
    }

#if __CUDA_ARCH__ >= 900
    cudaTriggerProgrammaticLaunchCompletion();
#endif
}

__global__ void __launch_bounds__(32) sym_finalize(float* __restrict__ out) {
#if __CUDA_ARCH__ >= 900
    cudaGridDependencySynchronize();  // full visibility of g_partial
#endif
    const int l = threadIdx.x;
    // 256 float2 partials = 128 float4; lane reads 4 coalesced float4 =
    // 8 (loss,count) pairs.
    const float4* p4 = reinterpret_cast<const float4*>(g_partial);
    double L = 0.0, C = 0.0;
#pragma unroll
    for (int i = 0; i < 4; i++) {
        const float4 v = p4[l + 32 * i];
        L += (double)v.x + (double)v.z;
        C += (double)v.y + (double)v.w;
    }
#pragma unroll
    for (int off = 16; off > 0; off >>= 1) {
        L += __shfl_down_sync(0xffffffffu, L, off);
        C += __shfl_down_sync(0xffffffffu, C, off);
    }
    if (l == 0) {
        const double c = C < 1.0 ? 1.0 : C;
        out[0] = (float)(L / c);
    }
}

extern "C" void kernel_launch(void* const* d_in, const int* in_sizes, int n_in,
                              void* d_out, int out_size) {
    const float* kp  = (const float*)d_in[0];  // [256, 512, 2] f32
    const int*   cls = (const int*)d_in[1];    // [256, 512] i32
    float* out = (float*)d_out;

    sym_per_batch<<<BATCH, 256>>>(kp, cls);

    // Finalize with Programmatic Dependent Launch to overlap its launch
    // latency with sym_per_batch execution.
    cudaLaunchConfig_t cfg = {};
    cfg.gridDim  = dim3(1, 1, 1);
    cfg.blockDim = dim3(32, 1, 1);
    cfg.dynamicSmemBytes = 0;
    cfg.stream = 0;
    cudaLaunchAttribute attr[1];
    attr[0].id = cudaLaunchAttributeProgrammaticStreamSerialization;
    attr[0].val.programmaticStreamSerializationAllowed = 1;
    cfg.attrs = attr;
    cfg.numAttrs = 1;

    cudaError_t e = cudaLaunchKernelEx(&cfg, sym_finalize, out);
    if (e != cudaSuccess) {
        // Fallback: plain serialized launch.
        sym_finalize<<<1, 32>>>(out);
    }
}

// round 10
// speedup vs baseline: 1.3258x; 1.3258x over previous
#include <cuda_runtime.h>
#include <cuda_bf16.h>
#include <cstdint>

// Closed-form per-(batch,class) reduction of the symmetric-pair loss.
// For a group of n points of one symmetric class (c in {0,1,2}), with
// u_i = x_i - CENTER_X:
//   sum_{i<j} (u_i+u_j)^2 = (n-2)*Sum(u^2) + (Sum u)^2
//   sum_{i<j} (y_i-y_j)^2 =  n   *Sum(y^2) - (Sum y)^2
//   #pairs                =  n(n-1)/2
// Both identities are exactly 0 for n in {0,1}.
//
// SINGLE kernel: R5-proven per-batch body (256 CTAs x 256 threads,
// 2 points/thread, all-float math, warp-parallel combine), then the
// canonical threadFenceReduction last-block finalize (ticket atomic —
// non-blocking by construction, no spin anywhere). Last CTA's warp 0
// reduces the 256 partials in parallel and writes the output.

#define CENTER_X 0.5f
#define BATCH 256
#define NPTS  512

__device__ float2       g_partial[BATCH];  // (loss, count) per batch
__device__ unsigned int g_ticket = 0;      // completion ticket (reset by last CTA)

__global__ void __launch_bounds__(256) sym_fused(const float* __restrict__ kp,
                                                 const int* __restrict__ cls,
                                                 float* __restrict__ out) {
    const int b = blockIdx.x;
    const int t = threadIdx.x;

    // Each thread handles 2 consecutive points: 1x float4 + 1x int2.
    const float4 p = reinterpret_cast<const float4*>(kp)[(size_t)b * 256 + t];
    const int2   c = reinterpret_cast<const int2*>(cls)[(size_t)b * 256 + t];

    float acc[15];  // [class][su, su2, sy, sy2, cn]
#pragma unroll
    for (int k = 0; k < 15; k++) acc[k] = 0.0f;

    const float ux[2] = {p.x - CENTER_X, p.z - CENTER_X};
    const float yy[2] = {p.y, p.w};
    const int   cc[2] = {c.x, c.y};
#pragma unroll
    for (int j = 0; j < 2; j++) {
#pragma unroll
        for (int k = 0; k < 3; k++) {
            if (cc[j] == k) {
                acc[k * 5 + 0] += ux[j];
                acc[k * 5 + 1]  = fmaf(ux[j], ux[j], acc[k * 5 + 1]);
                acc[k * 5 + 2] += yy[j];
                acc[k * 5 + 3]  = fmaf(yy[j], yy[j], acc[k * 5 + 3]);
                acc[k * 5 + 4] += 1.0f;
            }
        }
    }

    // Intra-warp reduction (shuffles).
#pragma unroll
    for (int off = 16; off > 0; off >>= 1) {
#pragma unroll
        for (int k = 0; k < 15; k++)
            acc[k] += __shfl_down_sync(0xffffffffu, acc[k], off);
    }

    // Cross-warp via shared memory (8 warps).
    __shared__ float sf[8][16];  // padded row
    __shared__ float stot[16];
    const int wid = t >> 5, lid = t & 31;
    if (lid == 0) {
#pragma unroll
        for (int k = 0; k < 15; k++) sf[wid][k] = acc[k];
    }
    __syncthreads();

    // Warp 0, lanes 0..14: each lane sums one accumulator type across 8 warps.
    if (wid == 0) {
        if (lid < 15) {
            float s = 0.0f;
#pragma unroll
            for (int w = 0; w < 8; w++) s += sf[w][lid];
            stot[lid] = s;
        }
        __syncwarp();
        if (lid == 0) {
            float loss = 0.0f, count = 0.0f;
#pragma unroll
            for (int k = 0; k < 3; k++) {
                const float SU  = stot[k * 5 + 0];
                const float SU2 = stot[k * 5 + 1];
                const float SY  = stot[k * 5 + 2];
                const float SY2 = stot[k * 5 + 3];
                const float n   = stot[k * 5 + 4];
                loss  += (n - 2.0f) * SU2 + SU * SU + n * SY2 - SY * SY;
                count += n * (n - 1.0f) * 0.5f;
            }
            g_partial[b] = make_float2(loss, count);
        }
    }

    // ---- last-CTA finalize (threadFenceReduction pattern; no spinning) ----
    __shared__ unsigned int s_ticket;
    __threadfence();  // order g_partial[b] before the ticket increment
    if (t == 0) s_ticket = atomicAdd(&g_ticket, 1u);
    __syncthreads();

    if (s_ticket == (unsigned int)(BATCH - 1)) {
        // All 256 partials are written and (via fences + atomic) visible.
        if (wid == 0) {
            __threadfence();  // acquire side
            const float4* p4 = reinterpret_cast<const float4*>(g_partial);
            double L = 0.0, C = 0.0;
#pragma unroll
            for (int i = 0; i < 4; i++) {
                const float4 v = p4[lid + 32 * i];
                L += (double)v.x + (double)v.z;
                C += (double)v.y + (double)v.w;
            }
#pragma unroll
            for (int off = 16; off > 0; off >>= 1) {
                L += __shfl_down_sync(0xffffffffu, L, off);
                C += __shfl_down_sync(0xffffffffu, C, off);
            }
            if (lid == 0) {
                const double cden = C < 1.0 ? 1.0 : C;
                out[0] = (float)(L / cden);
                g_ticket = 0;  // reset for next graph replay (deterministic)
            }
        }
    }
}

extern "C" void kernel_launch(void* const* d_in, const int* in_sizes, int n_in,
                              void* d_out, int out_size) {
    const float* kp  = (const float*)d_in[0];  // [256, 512, 2] f32
    const int*   cls = (const int*)d_in[1];    // [256, 512] i32
    float* out = (float*)d_out;

    sym_fused<<<BATCH, 256>>>(kp, cls, out);
}

// round 11
// speedup vs baseline: 1.6857x; 1.2714x over previous
#include <cuda_runtime.h>
#include <cuda_bf16.h>
#include <cstdint>

// Closed-form per-(batch,class) reduction of the symmetric-pair loss.
// For a group of n points of one symmetric class (c in {0,1,2}), with
// u_i = x_i - CENTER_X:
//   sum_{i<j} (u_i+u_j)^2 = (n-2)*Sum(u^2) + (Sum u)^2
//   sum_{i<j} (y_i-y_j)^2 =  n   *Sum(y^2) - (Sum y)^2
//   #pairs                =  n(n-1)/2
// Both identities are exactly 0 for n in {0,1}.
//
// SINGLE kernel. Per-CTA (loss,count) is accumulated into TWO global u64
// fixed-point counters via atomicAdd (integer addition is order-invariant
// -> bit-deterministic). The ticket-observing last CTA reads 2 words,
// divides, writes out, and resets state for the next graph replay.
// No 256-partial re-read, no FP64 shuffle tree on the critical path.

#define CENTER_X 0.5f
#define BATCH 256
#define NPTS  512
#define FP_SCALE 4294967296.0   // 2^32 fixed-point scale for loss

__device__ unsigned long long g_loss_fx = 0;  // sum of loss * 2^32
__device__ unsigned long long g_cnt_u   = 0;  // sum of pair counts (exact)
__device__ unsigned int       g_ticket  = 0;  // completion ticket

__device__ __forceinline__ unsigned long long ld_acq_u64(unsigned long long* p) {
    unsigned long long v;
    asm volatile("ld.global.acquire.gpu.b64 %0, [%1];" : "=l"(v) : "l"(p) : "memory");
    return v;
}

__global__ void __launch_bounds__(256) sym_fused(const float* __restrict__ kp,
                                                 const int* __restrict__ cls,
                                                 float* __restrict__ out) {
    const int b = blockIdx.x;
    const int t = threadIdx.x;

    // Each thread handles 2 consecutive points: 1x float4 + 1x int2.
    const float4 p = reinterpret_cast<const float4*>(kp)[(size_t)b * 256 + t];
    const int2   c = reinterpret_cast<const int2*>(cls)[(size_t)b * 256 + t];

    float acc[12];  // [class][su, su2, sy, sy2]
#pragma unroll
    for (int k = 0; k < 12; k++) acc[k] = 0.0f;

    const float ux[2] = {p.x - CENTER_X, p.z - CENTER_X};
    const float yy[2] = {p.y, p.w};
    const int   cc[2] = {c.x, c.y};
    int wcnt[3];  // warp-level class counts via ballot (uniform across lanes)
#pragma unroll
    for (int k = 0; k < 3; k++) {
        const unsigned m0 = __ballot_sync(0xffffffffu, cc[0] == k);
        const unsigned m1 = __ballot_sync(0xffffffffu, cc[1] == k);
        wcnt[k] = __popc(m0) + __popc(m1);
    }
#pragma unroll
    for (int j = 0; j < 2; j++) {
#pragma unroll
        for (int k = 0; k < 3; k++) {
            if (cc[j] == k) {
                acc[k * 4 + 0] += ux[j];
                acc[k * 4 + 1]  = fmaf(ux[j], ux[j], acc[k * 4 + 1]);
                acc[k * 4 + 2] += yy[j];
                acc[k * 4 + 3]  = fmaf(yy[j], yy[j], acc[k * 4 + 3]);
            }
        }
    }

    // Intra-warp reduction (shuffles): 12 float accumulators.
#pragma unroll
    for (int off = 16; off > 0; off >>= 1) {
#pragma unroll
        for (int k = 0; k < 12; k++)
            acc[k] += __shfl_down_sync(0xffffffffu, acc[k], off);
    }

    // Cross-warp via shared memory (8 warps publish 12 sums + 3 counts).
    __shared__ float sf[8][16];  // padded row
    __shared__ float stot[16];
    const int wid = t >> 5, lid = t & 31;
    if (lid == 0) {
#pragma unroll
        for (int k = 0; k < 12; k++) sf[wid][k] = acc[k];
#pragma unroll
        for (int k = 0; k < 3; k++)  sf[wid][12 + k] = (float)wcnt[k];
    }
    __syncthreads();

    // Warp 0, lanes 0..14: each lane sums one accumulator across 8 warps.
    if (wid == 0) {
        if (lid < 15) {
            float s = 0.0f;
#pragma unroll
            for (int w = 0; w < 8; w++) s += sf[w][lid];
            stot[lid] = s;
        }
        __syncwarp();
        if (lid == 0) {
            float loss = 0.0f, count = 0.0f;
#pragma unroll
            for (int k = 0; k < 3; k++) {
                const float SU  = stot[k * 4 + 0];
                const float SU2 = stot[k * 4 + 1];
                const float SY  = stot[k * 4 + 2];
                const float SY2 = stot[k * 4 + 3];
                const float n   = stot[12 + k];
                loss  += (n - 2.0f) * SU2 + SU * SU + n * SY2 - SY * SY;
                count += n * (n - 1.0f) * 0.5f;
            }
            // Deterministic accumulation: fixed-point integer atomics.
            const unsigned long long lfx =
                (unsigned long long)llrint((double)loss * FP_SCALE);
            const unsigned long long cu =
                (unsigned long long)llrintf(count);  // exact integer
            atomicAdd(&g_loss_fx, lfx);
            atomicAdd(&g_cnt_u, cu);
            __threadfence();  // order value atomics before the ticket
            const unsigned int v = atomicAdd(&g_ticket, 1u);
            if (v == (unsigned int)(BATCH - 1)) {
                // All 256 contributions complete and visible.
                const unsigned long long L = ld_acq_u64(&g_loss_fx);
                const unsigned long long C = ld_acq_u64(&g_cnt_u);
                const double loss_d = (double)L / FP_SCALE;
                const double cnt_d  = (C < 1ull) ? 1.0 : (double)C;
                out[0] = (float)(loss_d / cnt_d);
                // Reset for the next graph replay (deterministic).
                g_loss_fx = 0ull;
                g_cnt_u   = 0ull;
                g_ticket  = 0u;
            }
        }
    }
}

extern "C" void kernel_launch(void* const* d_in, const int* in_sizes, int n_in,
                              void* d_out, int out_size) {
    const float* kp  = (const float*)d_in[0];  // [256, 512, 2] f32
    const int*   cls = (const int*)d_in[1];    // [256, 512] i32
    float* out = (float*)d_out;

    sym_fused<<<BATCH, 256>>>(kp, cls, out);
}